// round 9
// baseline (speedup 1.0000x reference)
#include <cuda_runtime.h>

// Problem constants
#define BB   32
#define NN   2048
#define DD   65
#define HH   64
#define DSQ  (DD*DD)        // 4225
#define GSUB 64             // gram sub-tile rows
#define GNS  2              // sub-tiles per gram block
#define GCH  (GSUB*GNS)     // 128 rows per gram block
#define NGC  (NN/GCH)       // 16 partials per batch
#define OCH  64             // out chunk rows
#define NOC  (NN/OCH)       // 32
#define MMR  13             // mid tile rows (5*13 = 65)

typedef unsigned long long ull;

// Scratch (no allocations allowed)
__device__ float g_Gpart[BB * NGC * DSQ];   // partial Gram matrices (~8.6 MB)
__device__ float g_G[BB * DSQ];             // reduced Gram
__device__ float g_A[DSQ];                  // Wq^T Wk
__device__ float g_M[BB * DSQ];             // M = A * G * Wv^T per batch

// ---- packed fp32x2 helpers ----
__device__ __forceinline__ ull pack2(float x) {
    ull d; unsigned u = __float_as_uint(x);
    asm("mov.b64 %0, {%1, %1};" : "=l"(d) : "r"(u));
    return d;
}
__device__ __forceinline__ ull fma2(ull a, ull b, ull c) {
    ull d;
    asm("fma.rn.f32x2 %0, %1, %2, %3;" : "=l"(d) : "l"(a), "l"(b), "l"(c));
    return d;
}
__device__ __forceinline__ void unpack2(ull d, float& lo, float& hi) {
    unsigned a, b;
    asm("mov.b64 {%0, %1}, %2;" : "=r"(a), "=r"(b) : "l"(d));
    lo = __uint_as_float(a); hi = __uint_as_float(b);
}

// ---------------------------------------------------------------------------
// Kernel 0: A[i][j] = sum_h Wq[h][i] * Wk[h][j]   (grid 17, proven R1-R4)
// ---------------------------------------------------------------------------
__global__ void k_A(const float* __restrict__ Wq, const float* __restrict__ Wk) {
    int t = blockIdx.x * blockDim.x + threadIdx.x;
    if (t >= DSQ) return;
    int i = t / DD, j = t - i * DD;
    float s = 0.f;
#pragma unroll
    for (int h = 0; h < HH; ++h)
        s = fmaf(Wq[h * DD + i], Wk[h * DD + j], s);
    g_A[t] = s;
}

// ---------------------------------------------------------------------------
// Kernel 1: partial Gram, 128 rows / block as 2 x 64-row smem tiles. (R8, proven)
// ---------------------------------------------------------------------------
__global__ void __launch_bounds__(256, 4) k_gram(const float* __restrict__ x) {
    __shared__ __align__(16) float xs[GSUB * 68 + 16];

    const int b = blockIdx.y, c = blockIdx.x;
    const int tid = threadIdx.x;
    const int ty = tid >> 4, tx = tid & 15;
    const int p0 = tx, p1 = 16 + tx, p2 = (tx == 0) ? 32 : 33;

    int iv[5];
#pragma unroll
    for (int u = 0; u < 5; ++u) {
        int i = ty + 16 * u;
        iv[u] = (i < DD) ? i : (DD - 1);
    }

    ull acc[5][3];
#pragma unroll
    for (int u = 0; u < 5; ++u)
#pragma unroll
        for (int v = 0; v < 3; ++v) acc[u][v] = 0ull;

    for (int s = 0; s < GNS; ++s) {
        const float* xp = x + ((size_t)b * NN + (size_t)c * GCH + (size_t)s * GSUB) * DD;
        __syncthreads();
        for (int idx = tid; idx < GSUB * DD; idx += 256) {
            int r = idx / DD, col = idx - r * DD;
            xs[r * 68 + col] = xp[idx];
        }
        __syncthreads();

#pragma unroll 8
        for (int k = 0; k < GSUB; ++k) {
            const float* row = xs + k * 68;
            const ull* xd = (const ull*)row;
            ull b0 = xd[p0], b1 = xd[p1], b2 = xd[p2];
#pragma unroll
            for (int u = 0; u < 5; ++u) {
                ull ad = pack2(row[iv[u]]);
                acc[u][0] = fma2(ad, b0, acc[u][0]);
                acc[u][1] = fma2(ad, b1, acc[u][1]);
                acc[u][2] = fma2(ad, b2, acc[u][2]);
            }
        }
    }

    float* gp = g_Gpart + (size_t)(b * NGC + c) * DSQ;
    const int pv[3] = {p0, p1, p2};
#pragma unroll
    for (int u = 0; u < 5; ++u) {
        int i = ty + 16 * u;
        if (i >= DD) continue;
#pragma unroll
        for (int v = 0; v < 3; ++v) {
            int j0 = 2 * pv[v];
            float lo, hi;
            unpack2(acc[u][v], lo, hi);
            if (j0     < DD) gp[i * DD + j0]     = lo;
            if (j0 + 1 < DD) gp[i * DD + j0 + 1] = hi;
        }
    }
}

// ---------------------------------------------------------------------------
// Kernel 2: reduce 16 partial Grams -> g_G.  grid (17, 32). (proven)
// ---------------------------------------------------------------------------
__global__ void k_reduce() {
    const int b = blockIdx.y;
    int idx = blockIdx.x * 256 + threadIdx.x;
    if (idx >= DSQ) return;
    const float* gp = g_Gpart + (size_t)b * NGC * DSQ + idx;
    float s0 = 0.f, s1 = 0.f, s2 = 0.f, s3 = 0.f;
#pragma unroll
    for (int c = 0; c < NGC; c += 4) {
        s0 += gp[(c + 0) * DSQ];
        s1 += gp[(c + 1) * DSQ];
        s2 += gp[(c + 2) * DSQ];
        s3 += gp[(c + 3) * DSQ];
    }
    g_G[b * DSQ + idx] = (s0 + s1) + (s2 + s3);
}

// ---------------------------------------------------------------------------
// Kernel 3: per (batch b, row-tile t): T_tile = A_tile * G_b, then
// M_tile = T_tile * Wv^T  -> g_M.  Both phases are row-row dots:
//   T[i][j] = sum_k A[i][k] * G[j][k]   (G symmetric)
//   M[i][j] = sum_k T[i][k] * Wv[j][k]
// grid (5, 32), block 256. 4 interleaved accumulators per thread per phase.
// ---------------------------------------------------------------------------
__global__ void __launch_bounds__(256) k_midTM(const float* __restrict__ Wv) {
    __shared__ float SG[DSQ];        // G_b rows
    __shared__ float SWv[DSQ];       // Wv rows
    __shared__ float SA[MMR * DD];   // A tile rows
    __shared__ float ST[MMR * DD];   // T tile rows

    const int b = blockIdx.y, t = blockIdx.x;
    const int tid = threadIdx.x;
    const int gi0 = t * MMR;

    for (int idx = tid; idx < DSQ; idx += 256) {
        SG[idx]  = g_G[(size_t)b * DSQ + idx];
        SWv[idx] = Wv[idx];
    }
    for (int idx = tid; idx < MMR * DD; idx += 256)
        SA[idx] = g_A[gi0 * DD + idx];
    __syncthreads();

    int ii[4], jj[4];
#pragma unroll
    for (int m = 0; m < 4; ++m) {
        int idx = tid + 256 * m;
        int cl = (idx < MMR * DD) ? idx : (MMR * DD - 1);
        ii[m] = cl / DD;
        jj[m] = cl - ii[m] * DD;
    }

    // phase 1: T = A_tile * G
    {
        float s0 = 0.f, s1 = 0.f, s2 = 0.f, s3 = 0.f;
#pragma unroll 5
        for (int k = 0; k < DD; ++k) {
            s0 = fmaf(SA[ii[0] * DD + k], SG[jj[0] * DD + k], s0);
            s1 = fmaf(SA[ii[1] * DD + k], SG[jj[1] * DD + k], s1);
            s2 = fmaf(SA[ii[2] * DD + k], SG[jj[2] * DD + k], s2);
            s3 = fmaf(SA[ii[3] * DD + k], SG[jj[3] * DD + k], s3);
        }
        __syncthreads();
        float sv[4] = {s0, s1, s2, s3};
#pragma unroll
        for (int m = 0; m < 4; ++m) {
            int idx = tid + 256 * m;
            if (idx < MMR * DD) ST[idx] = sv[m];
        }
    }
    __syncthreads();

    // phase 2: M = T_tile * Wv^T
    {
        float s0 = 0.f, s1 = 0.f, s2 = 0.f, s3 = 0.f;
#pragma unroll 5
        for (int k = 0; k < DD; ++k) {
            s0 = fmaf(ST[ii[0] * DD + k], SWv[jj[0] * DD + k], s0);
            s1 = fmaf(ST[ii[1] * DD + k], SWv[jj[1] * DD + k], s1);
            s2 = fmaf(ST[ii[2] * DD + k], SWv[jj[2] * DD + k], s2);
            s3 = fmaf(ST[ii[3] * DD + k], SWv[jj[3] * DD + k], s3);
        }
        float sv[4] = {s0, s1, s2, s3};
        float* Mb = g_M + (size_t)b * DSQ + (size_t)gi0 * DD;
#pragma unroll
        for (int m = 0; m < 4; ++m) {
            int idx = tid + 256 * m;
            if (idx < MMR * DD) Mb[idx] = sv[m];
        }
    }
}

// ---------------------------------------------------------------------------
// Kernel 4: out_chunk = x_chunk * M_b, OCH=64, grid (32,32)=1024.
// acc pairs = output rows; a = natural x row-pair from xsT[k][r] (pitch 66);
// b = dup'd M pairs from Msd[k][2j..] (pitch 132). Per k: 2+5 LDS.64 + 10 FFMA2.
// Epilogue staged via smem (reuses xsT) then coalesced STG.
// ---------------------------------------------------------------------------
__global__ void __launch_bounds__(256, 4) k_out(const float* __restrict__ x,
                                                float* __restrict__ out) {
    extern __shared__ __align__(16) float smo[];
    float* Msd = smo;                 // 65*132 dup'd M
    float* xsT = smo + DD * 132;      // 65*66 transposed x; reused as osm[64*65]
    float* osm = xsT;

    const int b = blockIdx.y, c = blockIdx.x;
    const float* xp = x + ((size_t)b * NN + (size_t)c * OCH) * DD;
    float* op = out + ((size_t)b * NN + (size_t)c * OCH) * DD;
    const int tid = threadIdx.x;

    const float* Mg = g_M + (size_t)b * DSQ;
    for (int idx = tid; idx < DSQ; idx += 256) {
        int k = idx / DD, j = idx - k * DD;
        float v = Mg[idx];
        Msd[k * 132 + 2 * j]     = v;
        Msd[k * 132 + 2 * j + 1] = v;
    }
    for (int idx = tid; idx < OCH * DD; idx += 256) {
        int r = idx / DD, k = idx - r * DD;
        xsT[k * 66 + r] = xp[idx];
    }
    __syncthreads();

    const int ty = tid >> 4, tx = tid & 15;
    int jv[5];
#pragma unroll
    for (int v = 0; v < 5; ++v) {
        int j = ty + 16 * v;
        jv[v] = (j < DD) ? j : (DD - 1);   // clamp loads; stores guarded by real j
    }

    ull acc[2][5];
#pragma unroll
    for (int u = 0; u < 2; ++u)
#pragma unroll
        for (int v = 0; v < 5; ++v) acc[u][v] = 0ull;

    const ull* xu = (const ull*)xsT;   // pitch 33 ulls per k
    const ull* mu = (const ull*)Msd;   // pitch 66 ulls per k
#pragma unroll 5
    for (int k = 0; k < DD; ++k) {
        const ull* xk = xu + k * 33;
        ull a0 = xk[tx];
        ull a1 = xk[tx + 16];
        const ull* mk = mu + k * 66;
#pragma unroll
        for (int v = 0; v < 5; ++v) {
            ull m = mk[jv[v]];
            acc[0][v] = fma2(a0, m, acc[0][v]);
            acc[1][v] = fma2(a1, m, acc[1][v]);
        }
    }

    __syncthreads();   // all xsT reads done before osm overwrite

#pragma unroll
    for (int u = 0; u < 2; ++u) {
        int r0 = 2 * (tx + 16 * u);
#pragma unroll
        for (int v = 0; v < 5; ++v) {
            int j = ty + 16 * v;
            if (j < DD) {
                float lo, hi;
                unpack2(acc[u][v], lo, hi);
                osm[r0 * DD + j]       = lo;
                osm[(r0 + 1) * DD + j] = hi;
            }
        }
    }
    __syncthreads();

    for (int idx = tid; idx < OCH * DD; idx += 256)
        op[idx] = osm[idx];
}

// ---------------------------------------------------------------------------
extern "C" void kernel_launch(void* const* d_in, const int* in_sizes, int n_in,
                              void* d_out, int out_size) {
    const float* x  = (const float*)d_in[0];   // [32, 2048, 65]
    const float* Wq = (const float*)d_in[1];   // [64, 65]
    const float* Wk = (const float*)d_in[2];   // [64, 65]
    const float* Wv = (const float*)d_in[3];   // [65, 65]
    float* out = (float*)d_out;                // [32, 2048, 65]

    const int smem_out = (DD * 132 + DD * 66) * 4;   // 51480 B
    cudaFuncSetAttribute(k_out, cudaFuncAttributeMaxDynamicSharedMemorySize, smem_out);

    k_gram<<<dim3(NGC, BB), 256>>>(x);
    k_reduce<<<dim3(17, BB), 256>>>();
    k_A<<<17, 256>>>(Wq, Wk);
    k_midTM<<<dim3(5, BB), 256>>>(Wv);
    k_out<<<dim3(NOC, BB), 256, smem_out>>>(x, out);
}

// round 10
// speedup vs baseline: 1.0246x; 1.0246x over previous
#include <cuda_runtime.h>

// Problem constants
#define BB   32
#define NN   2048
#define DD   65
#define HH   64
#define DSQ  (DD*DD)        // 4225
#define GSUB 64             // gram sub-tile rows
#define GNS  2              // sub-tiles per gram block
#define GCH  (GSUB*GNS)     // 128 rows per gram block
#define NGC  (NN/GCH)       // 16 partials per batch
#define OCH  64             // out chunk rows
#define NOC  (NN/OCH)       // 32

typedef unsigned long long ull;

// Scratch (no allocations allowed)
__device__ float g_Gpart[BB * NGC * DSQ];   // partial Gram matrices (~8.6 MB)
__device__ float g_G[BB * DSQ];             // reduced Gram
__device__ float g_M[BB * DSQ];             // M = A * G * Wv^T per batch

// ---- packed fp32x2 helpers ----
__device__ __forceinline__ ull pack2(float x) {
    ull d; unsigned u = __float_as_uint(x);
    asm("mov.b64 %0, {%1, %1};" : "=l"(d) : "r"(u));
    return d;
}
__device__ __forceinline__ ull fma2(ull a, ull b, ull c) {
    ull d;
    asm("fma.rn.f32x2 %0, %1, %2, %3;" : "=l"(d) : "l"(a), "l"(b), "l"(c));
    return d;
}
__device__ __forceinline__ void unpack2(ull d, float& lo, float& hi) {
    unsigned a, b;
    asm("mov.b64 {%0, %1}, %2;" : "=r"(a), "=r"(b) : "l"(d));
    lo = __uint_as_float(a); hi = __uint_as_float(b);
}

// ---------------------------------------------------------------------------
// Kernel 1: partial Gram, 128 rows / block as 2 x 64-row smem tiles. (R8, proven)
// ---------------------------------------------------------------------------
__global__ void __launch_bounds__(256, 4) k_gram(const float* __restrict__ x) {
    __shared__ __align__(16) float xs[GSUB * 68 + 16];

    const int b = blockIdx.y, c = blockIdx.x;
    const int tid = threadIdx.x;
    const int ty = tid >> 4, tx = tid & 15;
    const int p0 = tx, p1 = 16 + tx, p2 = (tx == 0) ? 32 : 33;

    int iv[5];
#pragma unroll
    for (int u = 0; u < 5; ++u) {
        int i = ty + 16 * u;
        iv[u] = (i < DD) ? i : (DD - 1);
    }

    ull acc[5][3];
#pragma unroll
    for (int u = 0; u < 5; ++u)
#pragma unroll
        for (int v = 0; v < 3; ++v) acc[u][v] = 0ull;

    for (int s = 0; s < GNS; ++s) {
        const float* xp = x + ((size_t)b * NN + (size_t)c * GCH + (size_t)s * GSUB) * DD;
        __syncthreads();
        for (int idx = tid; idx < GSUB * DD; idx += 256) {
            int r = idx / DD, col = idx - r * DD;
            xs[r * 68 + col] = xp[idx];
        }
        __syncthreads();

#pragma unroll 8
        for (int k = 0; k < GSUB; ++k) {
            const float* row = xs + k * 68;
            const ull* xd = (const ull*)row;
            ull b0 = xd[p0], b1 = xd[p1], b2 = xd[p2];
#pragma unroll
            for (int u = 0; u < 5; ++u) {
                ull ad = pack2(row[iv[u]]);
                acc[u][0] = fma2(ad, b0, acc[u][0]);
                acc[u][1] = fma2(ad, b1, acc[u][1]);
                acc[u][2] = fma2(ad, b2, acc[u][2]);
            }
        }
    }

    float* gp = g_Gpart + (size_t)(b * NGC + c) * DSQ;
    const int pv[3] = {p0, p1, p2};
#pragma unroll
    for (int u = 0; u < 5; ++u) {
        int i = ty + 16 * u;
        if (i >= DD) continue;
#pragma unroll
        for (int v = 0; v < 3; ++v) {
            int j0 = 2 * pv[v];
            float lo, hi;
            unpack2(acc[u][v], lo, hi);
            if (j0     < DD) gp[i * DD + j0]     = lo;
            if (j0 + 1 < DD) gp[i * DD + j0 + 1] = hi;
        }
    }
}

// ---------------------------------------------------------------------------
// Kernel 2: reduce 16 partial Grams -> g_G.  grid (17, 32). (proven)
// ---------------------------------------------------------------------------
__global__ void k_reduce() {
    const int b = blockIdx.y;
    int idx = blockIdx.x * 256 + threadIdx.x;
    if (idx >= DSQ) return;
    const float* gp = g_Gpart + (size_t)b * NGC * DSQ + idx;
    float s0 = 0.f, s1 = 0.f, s2 = 0.f, s3 = 0.f;
#pragma unroll
    for (int c = 0; c < NGC; c += 4) {
        s0 += gp[(c + 0) * DSQ];
        s1 += gp[(c + 1) * DSQ];
        s2 += gp[(c + 2) * DSQ];
        s3 += gp[(c + 3) * DSQ];
    }
    g_G[b * DSQ + idx] = (s0 + s1) + (s2 + s3);
}

// ---------------------------------------------------------------------------
// Kernel 3 (fused mid, R8 proven): per batch b —
// A = Wq^T Wk; T = A*G; M = T*Wv^T -> g_M.  grid 32, block 256.
// ---------------------------------------------------------------------------
#define PITCH 68
#define ROWS80 (80 * PITCH)
__global__ void __launch_bounds__(256) k_mid2(const float* __restrict__ Wq,
                                              const float* __restrict__ Wk,
                                              const float* __restrict__ Wv) {
    extern __shared__ __align__(16) float sm[];
    float* SG = sm;
    float* SA = sm + ROWS80;
    float* ST = sm + 2 * ROWS80;
    float* SW = sm + 3 * ROWS80;

    const int b = blockIdx.x;
    const int tid = threadIdx.x;
    const int ty = tid >> 4, tx = tid & 15;
    const int p0 = tx, p1 = 16 + tx, p2 = (tx == 0) ? 32 : 33;
    const int pv[3] = {p0, p1, p2};

    for (int idx = tid; idx < DSQ; idx += 256) {
        int k = idx / DD, j = idx - k * DD;
        SG[k * PITCH + j] = g_G[(size_t)b * DSQ + idx];
    }
    for (int idx = tid; idx < HH * DD; idx += 256) {
        int h = idx / DD, i = idx - h * DD;
        ST[h * PITCH + i] = Wq[idx];
        SW[h * PITCH + i] = Wk[idx];
    }
    __syncthreads();

    // phase 0: A = Wq^T Wk
    {
        ull acc[5][3];
#pragma unroll
        for (int u = 0; u < 5; ++u)
#pragma unroll
            for (int v = 0; v < 3; ++v) acc[u][v] = 0ull;
#pragma unroll 4
        for (int h = 0; h < HH; ++h) {
            const float* qr = ST + h * PITCH;
            const ull* kr = (const ull*)(SW + h * PITCH);
            ull b0 = kr[p0], b1 = kr[p1], b2 = kr[p2];
#pragma unroll
            for (int u = 0; u < 5; ++u) {
                ull ad = pack2(qr[ty + 16 * u]);
                acc[u][0] = fma2(ad, b0, acc[u][0]);
                acc[u][1] = fma2(ad, b1, acc[u][1]);
                acc[u][2] = fma2(ad, b2, acc[u][2]);
            }
        }
        __syncthreads();
#pragma unroll
        for (int u = 0; u < 5; ++u) {
            ull* ap = (ull*)(SA + (ty + 16 * u) * PITCH);
#pragma unroll
            for (int v = 0; v < 3; ++v) ap[pv[v]] = acc[u][v];
        }
    }
    __syncthreads();

    // phase 1: T = A*G
    ull accT[5][3];
#pragma unroll
    for (int u = 0; u < 5; ++u)
#pragma unroll
        for (int v = 0; v < 3; ++v) accT[u][v] = 0ull;
#pragma unroll 5
    for (int k = 0; k < DD; ++k) {
        const ull* gr = (const ull*)(SG + k * PITCH);
        ull b0 = gr[p0], b1 = gr[p1], b2 = gr[p2];
#pragma unroll
        for (int u = 0; u < 5; ++u) {
            ull ad = pack2(SA[(ty + 16 * u) * PITCH + k]);
            accT[u][0] = fma2(ad, b0, accT[u][0]);
            accT[u][1] = fma2(ad, b1, accT[u][1]);
            accT[u][2] = fma2(ad, b2, accT[u][2]);
        }
    }
    __syncthreads();

#pragma unroll
    for (int u = 0; u < 5; ++u) {
        ull* tp = (ull*)(ST + (ty + 16 * u) * PITCH);
#pragma unroll
        for (int v = 0; v < 3; ++v) tp[pv[v]] = accT[u][v];
    }
    for (int idx = tid; idx < DSQ; idx += 256) {
        int j = idx / DD, k = idx - j * DD;
        SW[k * PITCH + j] = Wv[idx];
    }
    __syncthreads();

    // phase 2: M = T*Wv^T
    {
        ull acc[5][3];
#pragma unroll
        for (int u = 0; u < 5; ++u)
#pragma unroll
            for (int v = 0; v < 3; ++v) acc[u][v] = 0ull;
#pragma unroll 5
        for (int k = 0; k < DD; ++k) {
            const ull* wr = (const ull*)(SW + k * PITCH);
            ull b0 = wr[p0], b1 = wr[p1], b2 = wr[p2];
#pragma unroll
            for (int u = 0; u < 5; ++u) {
                ull ad = pack2(ST[(ty + 16 * u) * PITCH + k]);
                acc[u][0] = fma2(ad, b0, acc[u][0]);
                acc[u][1] = fma2(ad, b1, acc[u][1]);
                acc[u][2] = fma2(ad, b2, acc[u][2]);
            }
        }
        float* Mb = g_M + (size_t)b * DSQ;
#pragma unroll
        for (int u = 0; u < 5; ++u) {
            int i = ty + 16 * u;
            if (i >= DD) continue;
#pragma unroll
            for (int v = 0; v < 3; ++v) {
                int j0 = 2 * pv[v];
                float lo, hi;
                unpack2(acc[u][v], lo, hi);
                if (j0     < DD) Mb[i * DD + j0]     = lo;
                if (j0 + 1 < DD) Mb[i * DD + j0 + 1] = hi;
            }
        }
    }
}

// ---------------------------------------------------------------------------
// Kernel 4: out_chunk = x_chunk * M_b, OCH=64, grid (32,32)=1024.
// Pack2 b-side (min smem: 34.4 KB) -> 5 blocks/SM, 40 warps, occ ~62%.
// a = natural x row-pair from xsT[k][r] (pitch 66); b = pack2(M[k][j]).
// Epilogue staged via smem (reuses xsT) then coalesced STG.
// ---------------------------------------------------------------------------
__global__ void __launch_bounds__(256, 5) k_out(const float* __restrict__ x,
                                                float* __restrict__ out) {
    extern __shared__ __align__(16) float smo[];
    float* Ms  = smo;                 // 65*66
    float* xsT = smo + DD * 66;       // 65*66 transposed x; reused as osm[64*65]
    float* osm = xsT;

    const int b = blockIdx.y, c = blockIdx.x;
    const float* xp = x + ((size_t)b * NN + (size_t)c * OCH) * DD;
    float* op = out + ((size_t)b * NN + (size_t)c * OCH) * DD;
    const int tid = threadIdx.x;

    const float* Mg = g_M + (size_t)b * DSQ;
    for (int idx = tid; idx < DSQ; idx += 256) {
        int k = idx / DD, j = idx - k * DD;
        Ms[k * 66 + j] = Mg[idx];
    }
    for (int idx = tid; idx < OCH * DD; idx += 256) {
        int r = idx / DD, k = idx - r * DD;
        xsT[k * 66 + r] = xp[idx];
    }
    __syncthreads();

    const int ty = tid >> 4, tx = tid & 15;
    int jv[5];
#pragma unroll
    for (int v = 0; v < 5; ++v) {
        int j = ty + 16 * v;
        jv[v] = (j < DD) ? j : (DD - 1);   // clamp loads; stores guarded by real j
    }

    ull acc[2][5];
#pragma unroll
    for (int u = 0; u < 2; ++u)
#pragma unroll
        for (int v = 0; v < 5; ++v) acc[u][v] = 0ull;

    const ull* xu = (const ull*)xsT;   // pitch 33 ulls per k
#pragma unroll 5
    for (int k = 0; k < DD; ++k) {
        const ull* xk = xu + k * 33;
        ull a0 = xk[tx];
        ull a1 = xk[tx + 16];
        const float* mk = Ms + k * 66;
#pragma unroll
        for (int v = 0; v < 5; ++v) {
            ull m = pack2(mk[jv[v]]);
            acc[0][v] = fma2(a0, m, acc[0][v]);
            acc[1][v] = fma2(a1, m, acc[1][v]);
        }
    }

    __syncthreads();   // all xsT reads done before osm overwrite

#pragma unroll
    for (int u = 0; u < 2; ++u) {
        int r0 = 2 * (tx + 16 * u);
#pragma unroll
        for (int v = 0; v < 5; ++v) {
            int j = ty + 16 * v;
            if (j < DD) {
                float lo, hi;
                unpack2(acc[u][v], lo, hi);
                osm[r0 * DD + j]       = lo;
                osm[(r0 + 1) * DD + j] = hi;
            }
        }
    }
    __syncthreads();

    for (int idx = tid; idx < OCH * DD; idx += 256)
        op[idx] = osm[idx];
}

// ---------------------------------------------------------------------------
extern "C" void kernel_launch(void* const* d_in, const int* in_sizes, int n_in,
                              void* d_out, int out_size) {
    const float* x  = (const float*)d_in[0];   // [32, 2048, 65]
    const float* Wq = (const float*)d_in[1];   // [64, 65]
    const float* Wk = (const float*)d_in[2];   // [64, 65]
    const float* Wv = (const float*)d_in[3];   // [65, 65]
    float* out = (float*)d_out;                // [32, 2048, 65]

    const int smem_mid = (3 * ROWS80 + DD * PITCH) * 4;   // 82960 B
    const int smem_out = (DD * 66 + DD * 66) * 4;         // 34320 B
    cudaFuncSetAttribute(k_mid2, cudaFuncAttributeMaxDynamicSharedMemorySize, smem_mid);
    cudaFuncSetAttribute(k_out,  cudaFuncAttributeMaxDynamicSharedMemorySize, smem_out);

    k_gram<<<dim3(NGC, BB), 256>>>(x);
    k_reduce<<<dim3(17, BB), 256>>>();
    k_mid2<<<BB, 256, smem_mid>>>(Wq, Wk, Wv);
    k_out<<<dim3(NOC, BB), 256, smem_out>>>(x, out);
}

// round 11
// speedup vs baseline: 1.1400x; 1.1127x over previous
#include <cuda_runtime.h>

// Problem constants
#define BB   32
#define NN   2048
#define DD   65
#define HH   64
#define DSQ  (DD*DD)        // 4225
#define GSUB 64             // gram sub-tile rows
#define GNS  2              // sub-tiles per gram block
#define GCH  (GSUB*GNS)     // 128 rows per gram block
#define NGC  (NN/GCH)       // 16 partials per batch
#define OCH  128            // out chunk rows (R8 proven)
#define NOC  (NN/OCH)       // 16

typedef unsigned long long ull;

// Scratch (no allocations allowed)
__device__ float g_Gpart[BB * NGC * DSQ];   // partial Gram matrices (~8.6 MB)
__device__ float g_G[BB * DSQ];             // reduced Gram
__device__ float g_M[BB * DSQ];             // M = A * G * Wv^T per batch

// ---- packed fp32x2 helpers ----
__device__ __forceinline__ ull pack2(float x) {
    ull d; unsigned u = __float_as_uint(x);
    asm("mov.b64 %0, {%1, %1};" : "=l"(d) : "r"(u));
    return d;
}
__device__ __forceinline__ ull fma2(ull a, ull b, ull c) {
    ull d;
    asm("fma.rn.f32x2 %0, %1, %2, %3;" : "=l"(d) : "l"(a), "l"(b), "l"(c));
    return d;
}
__device__ __forceinline__ void unpack2(ull d, float& lo, float& hi) {
    unsigned a, b;
    asm("mov.b64 {%0, %1}, %2;" : "=r"(a), "=r"(b) : "l"(d));
    lo = __uint_as_float(a); hi = __uint_as_float(b);
}

// ---------------------------------------------------------------------------
// Kernel 1: partial Gram, 128 rows / block as 2 x 64-row smem tiles. (R8, proven)
// ---------------------------------------------------------------------------
__global__ void __launch_bounds__(256, 4) k_gram(const float* __restrict__ x) {
    __shared__ __align__(16) float xs[GSUB * 68 + 16];

    const int b = blockIdx.y, c = blockIdx.x;
    const int tid = threadIdx.x;
    const int ty = tid >> 4, tx = tid & 15;
    const int p0 = tx, p1 = 16 + tx, p2 = (tx == 0) ? 32 : 33;

    int iv[5];
#pragma unroll
    for (int u = 0; u < 5; ++u) {
        int i = ty + 16 * u;
        iv[u] = (i < DD) ? i : (DD - 1);
    }

    ull acc[5][3];
#pragma unroll
    for (int u = 0; u < 5; ++u)
#pragma unroll
        for (int v = 0; v < 3; ++v) acc[u][v] = 0ull;

    for (int s = 0; s < GNS; ++s) {
        const float* xp = x + ((size_t)b * NN + (size_t)c * GCH + (size_t)s * GSUB) * DD;
        __syncthreads();
        for (int idx = tid; idx < GSUB * DD; idx += 256) {
            int r = idx / DD, col = idx - r * DD;
            xs[r * 68 + col] = xp[idx];
        }
        __syncthreads();

#pragma unroll 8
        for (int k = 0; k < GSUB; ++k) {
            const float* row = xs + k * 68;
            const ull* xd = (const ull*)row;
            ull b0 = xd[p0], b1 = xd[p1], b2 = xd[p2];
#pragma unroll
            for (int u = 0; u < 5; ++u) {
                ull ad = pack2(row[iv[u]]);
                acc[u][0] = fma2(ad, b0, acc[u][0]);
                acc[u][1] = fma2(ad, b1, acc[u][1]);
                acc[u][2] = fma2(ad, b2, acc[u][2]);
            }
        }
    }

    float* gp = g_Gpart + (size_t)(b * NGC + c) * DSQ;
    const int pv[3] = {p0, p1, p2};
#pragma unroll
    for (int u = 0; u < 5; ++u) {
        int i = ty + 16 * u;
        if (i >= DD) continue;
#pragma unroll
        for (int v = 0; v < 3; ++v) {
            int j0 = 2 * pv[v];
            float lo, hi;
            unpack2(acc[u][v], lo, hi);
            if (j0     < DD) gp[i * DD + j0]     = lo;
            if (j0 + 1 < DD) gp[i * DD + j0 + 1] = hi;
        }
    }
}

// ---------------------------------------------------------------------------
// Kernel 2: reduce 16 partial Grams -> g_G.  grid (17, 32). (proven)
// ---------------------------------------------------------------------------
__global__ void k_reduce() {
    const int b = blockIdx.y;
    int idx = blockIdx.x * 256 + threadIdx.x;
    if (idx >= DSQ) return;
    const float* gp = g_Gpart + (size_t)b * NGC * DSQ + idx;
    float s0 = 0.f, s1 = 0.f, s2 = 0.f, s3 = 0.f;
#pragma unroll
    for (int c = 0; c < NGC; c += 4) {
        s0 += gp[(c + 0) * DSQ];
        s1 += gp[(c + 1) * DSQ];
        s2 += gp[(c + 2) * DSQ];
        s3 += gp[(c + 3) * DSQ];
    }
    g_G[b * DSQ + idx] = (s0 + s1) + (s2 + s3);
}

// ---------------------------------------------------------------------------
// Kernel 3: mid chain, tiled 3 ways per batch. grid (3, 32) = 96 blocks.
// Block (t,b) computes output rows i in [32t, 32t+32) through all phases:
//   phase 0: A[i][j] = sum_h Wq[h][i] * Wk[h][j]        (A-tile -> B3)
//   phase 1: T[i][j] = sum_k A[i][k] * G[k][j]          (T-tile -> B3)
//   phase 2: M[i][j] = sum_k T[i][k] * WvT[k][j]        -> g_M
// Buffers: B1: Wq -> Wv^T;  B2: Wk -> G;  B3: A-tile -> T-tile.
// FFMA2 2x3 micro-tile (pair dim = output cols), clamped loads, guarded stores.
// ---------------------------------------------------------------------------
__global__ void __launch_bounds__(256) k_mid3(const float* __restrict__ Wq,
                                              const float* __restrict__ Wk,
                                              const float* __restrict__ Wv) {
    __shared__ __align__(16) float B1[DD * 68];   // 17.7 KB
    __shared__ __align__(16) float B2[DD * 68];   // 17.7 KB
    __shared__ __align__(16) float B3[32 * 68];   //  8.7 KB

    const int b = blockIdx.y, t = blockIdx.x;     // t in 0..2
    const int tid = threadIdx.x;
    const int ty = tid >> 4, tx = tid & 15;
    const int p0 = tx, p1 = 16 + tx, p2 = (tx == 0) ? 32 : 33;
    const int pv[3] = {p0, p1, p2};
    const int i0 = t * 32;

    int iv[2];   // clamped global row index for phase-0 scalar loads
#pragma unroll
    for (int u = 0; u < 2; ++u) {
        int i = i0 + ty + 16 * u;
        iv[u] = (i < DD) ? i : (DD - 1);
    }

    // ---- stage Wq -> B1, Wk -> B2 ----
    for (int idx = tid; idx < HH * DD; idx += 256) {
        int h = idx / DD, i = idx - h * DD;
        B1[h * 68 + i] = Wq[idx];
        B2[h * 68 + i] = Wk[idx];
    }
    __syncthreads();

    // ---- phase 0: A-tile ----
    {
        ull acc[2][3];
#pragma unroll
        for (int u = 0; u < 2; ++u)
#pragma unroll
            for (int v = 0; v < 3; ++v) acc[u][v] = 0ull;
#pragma unroll 8
        for (int h = 0; h < HH; ++h) {
            const ull* kr = (const ull*)(B2 + h * 68);
            ull b0 = kr[p0], b1 = kr[p1], b2 = kr[p2];
            const float* qr = B1 + h * 68;
#pragma unroll
            for (int u = 0; u < 2; ++u) {
                ull ad = pack2(qr[iv[u]]);
                acc[u][0] = fma2(ad, b0, acc[u][0]);
                acc[u][1] = fma2(ad, b1, acc[u][1]);
                acc[u][2] = fma2(ad, b2, acc[u][2]);
            }
        }
        __syncthreads();   // all Wq/Wk reads done
#pragma unroll
        for (int u = 0; u < 2; ++u) {
            ull* ap = (ull*)(B3 + (ty + 16 * u) * 68);
#pragma unroll
            for (int v = 0; v < 3; ++v) ap[pv[v]] = acc[u][v];
        }
    }
    // restage B2 <- G_b
    for (int idx = tid; idx < DSQ; idx += 256) {
        int k = idx / DD, j = idx - k * DD;
        B2[k * 68 + j] = g_G[(size_t)b * DSQ + idx];
    }
    __syncthreads();

    // ---- phase 1: T-tile = A-tile * G ----
    ull accT[2][3];
#pragma unroll
    for (int u = 0; u < 2; ++u)
#pragma unroll
        for (int v = 0; v < 3; ++v) accT[u][v] = 0ull;
#pragma unroll 5
    for (int k = 0; k < DD; ++k) {
        const ull* gr = (const ull*)(B2 + k * 68);
        ull b0 = gr[p0], b1 = gr[p1], b2 = gr[p2];
#pragma unroll
        for (int u = 0; u < 2; ++u) {
            ull ad = pack2(B3[(ty + 16 * u) * 68 + k]);
            accT[u][0] = fma2(ad, b0, accT[u][0]);
            accT[u][1] = fma2(ad, b1, accT[u][1]);
            accT[u][2] = fma2(ad, b2, accT[u][2]);
        }
    }
    __syncthreads();   // all A reads done; B1 (Wq) dead

#pragma unroll
    for (int u = 0; u < 2; ++u) {
        ull* tp = (ull*)(B3 + (ty + 16 * u) * 68);
#pragma unroll
        for (int v = 0; v < 3; ++v) tp[pv[v]] = accT[u][v];
    }
    // restage B1 <- Wv^T  (B1[k][j] = Wv[j][k], coalesced reads)
    for (int idx = tid; idx < DSQ; idx += 256) {
        int j = idx / DD, k = idx - j * DD;
        B1[k * 68 + j] = Wv[idx];
    }
    __syncthreads();

    // ---- phase 2: M-tile = T-tile * Wv^T ----
    {
        ull acc[2][3];
#pragma unroll
        for (int u = 0; u < 2; ++u)
#pragma unroll
            for (int v = 0; v < 3; ++v) acc[u][v] = 0ull;
#pragma unroll 5
        for (int k = 0; k < DD; ++k) {
            const ull* wr = (const ull*)(B1 + k * 68);
            ull b0 = wr[p0], b1 = wr[p1], b2 = wr[p2];
#pragma unroll
            for (int u = 0; u < 2; ++u) {
                ull ad = pack2(B3[(ty + 16 * u) * 68 + k]);
                acc[u][0] = fma2(ad, b0, acc[u][0]);
                acc[u][1] = fma2(ad, b1, acc[u][1]);
                acc[u][2] = fma2(ad, b2, acc[u][2]);
            }
        }
        float* Mb = g_M + (size_t)b * DSQ;
#pragma unroll
        for (int u = 0; u < 2; ++u) {
            int i = i0 + ty + 16 * u;
            if (i >= DD) continue;
#pragma unroll
            for (int v = 0; v < 3; ++v) {
                int j0 = 2 * pv[v];
                float lo, hi;
                unpack2(acc[u][v], lo, hi);
                if (j0     < DD) Mb[i * DD + j0]     = lo;
                if (j0 + 1 < DD) Mb[i * DD + j0 + 1] = hi;
            }
        }
    }
}

// ---------------------------------------------------------------------------
// Kernel 4: out_chunk = x_chunk * M_b, OCH=128, grid (16,32)=512. (R8, proven)
// acc pairs = output rows; a = natural x row-pairs from xsT[k][r] (pitch 130);
// b = pack2(M[k][j]) one column at a time. Epilogue staged via smem.
// ---------------------------------------------------------------------------
__global__ void __launch_bounds__(256, 4) k_out(const float* __restrict__ x,
                                                float* __restrict__ out) {
    extern __shared__ __align__(16) float smo[];
    float* Ms  = smo;                 // 65*66
    float* xsT = smo + DD * 66;       // 65*130 transposed x; reused as osm[128*65]
    float* osm = xsT;

    const int b = blockIdx.y, c = blockIdx.x;
    const float* xp = x + ((size_t)b * NN + (size_t)c * OCH) * DD;
    float* op = out + ((size_t)b * NN + (size_t)c * OCH) * DD;
    const int tid = threadIdx.x;

    const float* Mg = g_M + (size_t)b * DSQ;
    for (int idx = tid; idx < DSQ; idx += 256) {
        int k = idx / DD, j = idx - k * DD;
        Ms[k * 66 + j] = Mg[idx];
    }
    for (int idx = tid; idx < OCH * DD; idx += 256) {
        int r = idx / DD, k = idx - r * DD;
        xsT[k * 130 + r] = xp[idx];
    }
    __syncthreads();

    const int ty = tid >> 4, tx = tid & 15;
    int jv[5];
#pragma unroll
    for (int v = 0; v < 5; ++v) {
        int j = ty + 16 * v;
        jv[v] = (j < DD) ? j : (DD - 1);   // clamp loads; stores guarded by real j
    }

    ull acc[4][5];
#pragma unroll
    for (int u = 0; u < 4; ++u)
#pragma unroll
        for (int v = 0; v < 5; ++v) acc[u][v] = 0ull;

    const ull* xu = (const ull*)xsT;   // pitch 65 ulls per k
#pragma unroll 5
    for (int k = 0; k < DD; ++k) {
        const ull* xk = xu + k * 65;
        ull a0 = xk[tx];
        ull a1 = xk[tx + 16];
        ull a2 = xk[tx + 32];
        ull a3 = xk[tx + 48];
        const float* mk = Ms + k * 66;
#pragma unroll
        for (int v = 0; v < 5; ++v) {
            ull m = pack2(mk[jv[v]]);
            acc[0][v] = fma2(a0, m, acc[0][v]);
            acc[1][v] = fma2(a1, m, acc[1][v]);
            acc[2][v] = fma2(a2, m, acc[2][v]);
            acc[3][v] = fma2(a3, m, acc[3][v]);
        }
    }

    __syncthreads();   // all xsT reads done before osm overwrite

#pragma unroll
    for (int u = 0; u < 4; ++u) {
        int r0 = 2 * (tx + 16 * u);
#pragma unroll
        for (int v = 0; v < 5; ++v) {
            int j = ty + 16 * v;
            if (j < DD) {
                float lo, hi;
                unpack2(acc[u][v], lo, hi);
                osm[r0 * DD + j]       = lo;
                osm[(r0 + 1) * DD + j] = hi;
            }
        }
    }
    __syncthreads();

    for (int idx = tid; idx < OCH * DD; idx += 256)
        op[idx] = osm[idx];
}

// ---------------------------------------------------------------------------
extern "C" void kernel_launch(void* const* d_in, const int* in_sizes, int n_in,
                              void* d_out, int out_size) {
    const float* x  = (const float*)d_in[0];   // [32, 2048, 65]
    const float* Wq = (const float*)d_in[1];   // [64, 65]
    const float* Wk = (const float*)d_in[2];   // [64, 65]
    const float* Wv = (const float*)d_in[3];   // [65, 65]
    float* out = (float*)d_out;                // [32, 2048, 65]

    const int smem_out = (DD * 66 + DD * 130) * 4;   // 50960 B
    cudaFuncSetAttribute(k_out, cudaFuncAttributeMaxDynamicSharedMemorySize, smem_out);

    k_gram<<<dim3(NGC, BB), 256>>>(x);
    k_reduce<<<dim3(17, BB), 256>>>();
    k_mid3<<<dim3(3, BB), 256>>>(Wq, Wk, Wv);
    k_out<<<dim3(NOC, BB), 256, smem_out>>>(x, out);
}